// round 1
// baseline (speedup 1.0000x reference)
#include <cuda_runtime.h>
#include <math.h>
#include <stdint.h>

// Problem constants
#define T_LEN 512
#define NBATCH 64
#define EMB 512
#define HID 512
#define G4 2048          // 4*HID
#define NVOCAB 10000

// Persistent scan config
#define SCAN_BLOCKS 128
#define SCAN_THREADS 128
#define UNITS_PER_BLOCK 4    // 512 / 128

// -------- device scratch (static allocation; no cudaMalloc allowed) --------
__device__ float g_E0[(size_t)NVOCAB * G4];            // emb_table @ Wih0^T + b0   (80 MB)
__device__ float g_h1[(size_t)T_LEN * NBATCH * HID];   // layer0 outputs            (64 MB)
__device__ float g_xW1[(size_t)T_LEN * NBATCH * G4];   // h1 @ Wih1^T + b1          (256 MB)
__device__ float g_hbuf[2][HID * NBATCH];              // ping-pong h state, [unit][batch]
__device__ unsigned g_bar;                             // grid barrier counter

// ---------------------------------------------------------------------------
// zero-init kernel: h state buffer 0 and the barrier counter
// ---------------------------------------------------------------------------
__global__ void zero_init_kernel() {
    int i = blockIdx.x * blockDim.x + threadIdx.x;
    if (i < HID * NBATCH) g_hbuf[0][i] = 0.0f;
    if (i == 0) g_bar = 0u;
}

// ---------------------------------------------------------------------------
// GEMM: C[M][2048] = A[M][512] @ W[2048][512]^T + (b1 + b2)
//   A == nullptr  -> A = g_h1
//   dst_sel: 0 -> g_E0, 1 -> g_xW1
// Tiles: BM=128, BN=64, BK=16; 256 threads; 8x4 per-thread microtile.
// ---------------------------------------------------------------------------
__global__ __launch_bounds__(256) void gemm_bias_kernel(
    const float* __restrict__ A_in,
    const float* __restrict__ W,
    const float* __restrict__ b1,
    const float* __restrict__ b2,
    int dst_sel, int M)
{
    const float* A = A_in ? A_in : g_h1;
    float* C = dst_sel ? g_xW1 : g_E0;

    __shared__ float As[16][132];   // [k][m], padded
    __shared__ float Ws[16][64];    // [k][n]

    int tid = threadIdx.x;
    int m0 = blockIdx.y * 128;
    int n0 = blockIdx.x * 64;
    int tm = tid >> 4;      // 0..15
    int tn = tid & 15;      // 0..15

    float acc[8][4];
#pragma unroll
    for (int i = 0; i < 8; i++)
#pragma unroll
        for (int j = 0; j < 4; j++) acc[i][j] = 0.0f;

    for (int k0 = 0; k0 < 512; k0 += 16) {
        // Load A tile: 128 rows x 16 k = 512 float4; 2 per thread
#pragma unroll
        for (int i = 0; i < 2; i++) {
            int idx = tid + i * 256;
            int row = idx >> 2;
            int kv = (idx & 3) * 4;
            int gr = m0 + row;
            float4 v = make_float4(0.f, 0.f, 0.f, 0.f);
            if (gr < M) v = *(const float4*)(A + (size_t)gr * 512 + k0 + kv);
            As[kv + 0][row] = v.x;
            As[kv + 1][row] = v.y;
            As[kv + 2][row] = v.z;
            As[kv + 3][row] = v.w;
        }
        // Load W tile: 64 rows x 16 k = 256 float4; 1 per thread
        {
            int row = tid >> 2;
            int kv = (tid & 3) * 4;
            float4 v = *(const float4*)(W + (size_t)(n0 + row) * 512 + k0 + kv);
            Ws[kv + 0][row] = v.x;
            Ws[kv + 1][row] = v.y;
            Ws[kv + 2][row] = v.z;
            Ws[kv + 3][row] = v.w;
        }
        __syncthreads();

#pragma unroll
        for (int k = 0; k < 16; k++) {
            float a[8], w[4];
            *(float4*)(a) = *(const float4*)&As[k][tm * 8];
            *(float4*)(a + 4) = *(const float4*)&As[k][tm * 8 + 4];
            *(float4*)(w) = *(const float4*)&Ws[k][tn * 4];
#pragma unroll
            for (int i = 0; i < 8; i++)
#pragma unroll
                for (int j = 0; j < 4; j++)
                    acc[i][j] += a[i] * w[j];
        }
        __syncthreads();
    }

    int n = n0 + tn * 4;
    float bb[4];
#pragma unroll
    for (int j = 0; j < 4; j++) bb[j] = b1[n + j] + b2[n + j];

#pragma unroll
    for (int i = 0; i < 8; i++) {
        int m = m0 + tm * 8 + i;
        if (m < M) {
            float4 v;
            v.x = acc[i][0] + bb[0];
            v.y = acc[i][1] + bb[1];
            v.z = acc[i][2] + bb[2];
            v.w = acc[i][3] + bb[3];
            *(float4*)(C + (size_t)m * G4 + n) = v;
        }
    }
}

__device__ __forceinline__ float sigmoidf_(float x) {
    return 1.0f / (1.0f + expf(-x));
}

// ---------------------------------------------------------------------------
// Persistent LSTM scan. One launch per layer, 512 steps inside, grid barrier
// between steps. 128 blocks (1/SM, guaranteed co-resident on 148+ SM GB300).
//
// Layer 0 (src != nullptr): xW gathered from g_E0 by src; writes g_h1 sequence.
// Layer 1 (src == nullptr): xW from g_xW1; writes final_out at t == sen_len-1.
//
// Block b owns hidden units [4b, 4b+4). Thread (ug = tid/32, lane) owns
// batches {lane, lane+32} for unit 4b+ug, all 4 gates. c-state in registers.
// smem: Whh tile 16x512 (loaded once) + h staged [k][batch] (per step).
// ---------------------------------------------------------------------------
__global__ __launch_bounds__(SCAN_THREADS) void lstm_scan_kernel(
    const int* __restrict__ src,        // nullptr for layer 1
    const float* __restrict__ Whh,
    const int* __restrict__ sen_len,    // nullptr for layer 0
    float* __restrict__ final_out)      // nullptr for layer 0
{
    extern __shared__ float sm[];
    float* sh_w = sm;                 // [16][512]  (r = ug*4+gate)
    float* sh_h = sm + 16 * 512;      // [512][64]  (k-major, batch fast)

    const int tid = threadIdx.x;
    const int u0 = blockIdx.x * UNITS_PER_BLOCK;
    const int lane = tid & 31;
    const int ug = tid >> 5;          // 0..3
    const int b0 = lane;
    const int b1 = lane + 32;
    const unsigned nblk = gridDim.x;

    // Load this block's 16 Whh rows into smem (once).
    for (int idx = tid; idx < 16 * 128; idx += SCAN_THREADS) {
        int r = idx >> 7;             // 0..15
        int kv = (idx & 127) * 4;
        int ugl = r >> 2, gt = r & 3;
        float4 v = *(const float4*)(Whh + (size_t)(gt * 512 + u0 + ugl) * 512 + kv);
        *(float4*)&sh_w[r * 512 + kv] = v;
    }

    float c0 = 0.0f, c1 = 0.0f;
    int sl0 = -1, sl1 = -1;
    if (sen_len) { sl0 = sen_len[b0]; sl1 = sen_len[b1]; }

    const float* wrow = &sh_w[(ug * 4) * 512];

    for (int t = 0; t < T_LEN; t++) {
        // Stage h_prev (L2, bypass L1 — other SMs wrote it) into smem.
        const float4* hsrc = (const float4*)g_hbuf[t & 1];
        for (int idx = tid; idx < (HID * NBATCH) / 4; idx += SCAN_THREADS) {
            float4 v = __ldcg(hsrc + idx);
            *(float4*)&sh_h[idx * 4] = v;
        }
        __syncthreads();   // smem ready (also covers sh_w on first iter)

        // Input-projection terms (precomputed GEMM results)
        float acc0[4], acc1[4];
        if (src) {
            int r0 = src[t * NBATCH + b0];
            int r1 = src[t * NBATCH + b1];
            const float* e0 = g_E0 + (size_t)r0 * G4;
            const float* e1 = g_E0 + (size_t)r1 * G4;
#pragma unroll
            for (int gt = 0; gt < 4; gt++) {
                acc0[gt] = e0[gt * 512 + u0 + ug];
                acc1[gt] = e1[gt * 512 + u0 + ug];
            }
        } else {
            const float* x0 = g_xW1 + (size_t)(t * NBATCH + b0) * G4;
            const float* x1 = g_xW1 + (size_t)(t * NBATCH + b1) * G4;
#pragma unroll
            for (int gt = 0; gt < 4; gt++) {
                acc0[gt] = x0[gt * 512 + u0 + ug];
                acc1[gt] = x1[gt * 512 + u0 + ug];
            }
        }

        // Recurrent GEMM: gates += h_prev @ Whh^T   (per-thread: 2 batches x 4 gates)
#pragma unroll 8
        for (int k = 0; k < 512; k++) {
            float h0 = sh_h[k * 64 + b0];
            float h1v = sh_h[k * 64 + b1];
#pragma unroll
            for (int gt = 0; gt < 4; gt++) {
                float w = wrow[gt * 512 + k];
                acc0[gt] += h0 * w;
                acc1[gt] += h1v * w;
            }
        }

        // Pointwise LSTM cell
        float* hdst = g_hbuf[(t + 1) & 1];
        int u = u0 + ug;

        float i0 = sigmoidf_(acc0[0]);
        float f0 = sigmoidf_(acc0[1]);
        float g0 = tanhf(acc0[2]);
        float o0 = sigmoidf_(acc0[3]);
        c0 = f0 * c0 + i0 * g0;
        float h0n = o0 * tanhf(c0);

        float i1 = sigmoidf_(acc1[0]);
        float f1 = sigmoidf_(acc1[1]);
        float g1 = tanhf(acc1[2]);
        float o1 = sigmoidf_(acc1[3]);
        c1 = f1 * c1 + i1 * g1;
        float h1n = o1 * tanhf(c1);

        hdst[u * 64 + b0] = h0n;
        hdst[u * 64 + b1] = h1n;

        if (src) {
            // layer 0: record full sequence for layer 1's input GEMM
            g_h1[(size_t)(t * NBATCH + b0) * HID + u] = h0n;
            g_h1[(size_t)(t * NBATCH + b1) * HID + u] = h1n;
        } else {
            if (t == sl0 - 1) final_out[b0 * HID + u] = h0n;
            if (t == sl1 - 1) final_out[b1 * HID + u] = h1n;
        }

        // Grid barrier: make h writes globally visible, then sense via counter.
        __threadfence();
        __syncthreads();
        if (tid == 0) {
            atomicAdd(&g_bar, 1u);
            unsigned tgt = nblk * (unsigned)(t + 1);
            while (*(volatile unsigned*)&g_bar < tgt) { }
        }
        __syncthreads();
    }
}

// ---------------------------------------------------------------------------
extern "C" void kernel_launch(void* const* d_in, const int* in_sizes, int n_in,
                              void* d_out, int out_size)
{
    const int*   src       = (const int*)  d_in[0];
    const int*   sen_len   = (const int*)  d_in[1];
    const float* emb_table = (const float*)d_in[2];
    const float* Wih0      = (const float*)d_in[3];
    const float* Whh0      = (const float*)d_in[4];
    const float* bih0      = (const float*)d_in[5];
    const float* bhh0      = (const float*)d_in[6];
    const float* Wih1      = (const float*)d_in[7];
    const float* Whh1      = (const float*)d_in[8];
    const float* bih1      = (const float*)d_in[9];
    const float* bhh1      = (const float*)d_in[10];
    float* out = (float*)d_out;

    const size_t scan_smem = (size_t)(16 * 512 + 512 * 64) * sizeof(float); // 160 KB
    cudaFuncSetAttribute(lstm_scan_kernel,
                         cudaFuncAttributeMaxDynamicSharedMemorySize,
                         (int)scan_smem);

    // Phase 0: E0 = emb_table @ Wih0^T + b0   (10000 x 2048)
    {
        dim3 grid(G4 / 64, (NVOCAB + 127) / 128);
        gemm_bias_kernel<<<grid, 256>>>(emb_table, Wih0, bih0, bhh0, /*dst=E0*/0, NVOCAB);
    }

    // Phase 1: layer-0 scan
    zero_init_kernel<<<64, 512>>>();
    lstm_scan_kernel<<<SCAN_BLOCKS, SCAN_THREADS, scan_smem>>>(
        src, Whh0, nullptr, nullptr);

    // Phase 2: xW1 = h1 @ Wih1^T + b1   (32768 x 2048)
    {
        dim3 grid(G4 / 64, (T_LEN * NBATCH) / 128);
        gemm_bias_kernel<<<grid, 256>>>(nullptr, Wih1, bih1, bhh1, /*dst=xW1*/1,
                                        T_LEN * NBATCH);
    }

    // Phase 3: layer-1 scan (+ final gather at sen_len-1)
    zero_init_kernel<<<64, 512>>>();
    lstm_scan_kernel<<<SCAN_BLOCKS, SCAN_THREADS, scan_smem>>>(
        nullptr, Whh1, sen_len, out);
}

// round 2
// speedup vs baseline: 1.4519x; 1.4519x over previous
#include <cuda_runtime.h>
#include <math.h>
#include <stdint.h>

// Problem constants
#define T_LEN 512
#define NBATCH 64
#define EMB 512
#define HID 512
#define G4 2048          // 4*HID
#define NVOCAB 10000

// Persistent scan config
#define SCAN_BLOCKS 128
#define SCAN_THREADS 128

// -------- device scratch (static allocation; no cudaMalloc allowed) --------
__device__ float g_E0[(size_t)NVOCAB * G4];            // emb_table @ Wih0^T + b0   (80 MB)
__device__ float g_h1[(size_t)T_LEN * NBATCH * HID];   // layer0 outputs [t*64+b][u] (64 MB)
__device__ float g_xW1[(size_t)T_LEN * NBATCH * G4];   // h1 @ Wih1^T + b1          (256 MB)
__device__ float g_hbuf[2][NBATCH * HID];              // ping-pong h, [batch][unit], tf32-rounded
__device__ unsigned g_flags[SCAN_BLOCKS];              // per-block arrival flags
__device__ unsigned g_release;                         // barrier release word

// ---------------------------------------------------------------------------
// helpers
// ---------------------------------------------------------------------------
__device__ __forceinline__ unsigned f2tf(float f) {
    unsigned r; asm("cvt.rna.tf32.f32 %0, %1;" : "=r"(r) : "f"(f)); return r;
}
__device__ __forceinline__ float tf32f(float f) {
    return __uint_as_float(f2tf(f));
}
__device__ __forceinline__ void mma_tf32(float* c, const unsigned* a, const unsigned* b) {
    asm("mma.sync.aligned.m16n8k8.row.col.f32.tf32.tf32.f32 "
        "{%0,%1,%2,%3}, {%4,%5,%6,%7}, {%8,%9}, {%0,%1,%2,%3};"
        : "+f"(c[0]), "+f"(c[1]), "+f"(c[2]), "+f"(c[3])
        : "r"(a[0]), "r"(a[1]), "r"(a[2]), "r"(a[3]), "r"(b[0]), "r"(b[1]));
}
__device__ __forceinline__ unsigned ldvol(const unsigned* p) {
    unsigned v; asm volatile("ld.volatile.global.u32 %0, [%1];" : "=r"(v) : "l"(p)); return v;
}
__device__ __forceinline__ void stvol(unsigned* p, unsigned v) {
    asm volatile("st.volatile.global.u32 [%0], %1;" :: "l"(p), "r"(v));
}
__device__ __forceinline__ float sigmoidf_(float x) {
    return 1.0f / (1.0f + expf(-x));
}

// ---------------------------------------------------------------------------
// zero-init: h state buffer 0 + barrier state
// ---------------------------------------------------------------------------
__global__ void zero_init_kernel() {
    int i = blockIdx.x * blockDim.x + threadIdx.x;
    if (i < HID * NBATCH) ((float*)g_hbuf)[i] = 0.0f;   // g_hbuf[0]
    if (i < SCAN_BLOCKS) g_flags[i] = 0u;
    if (i == 0) g_release = 0u;
}

// ---------------------------------------------------------------------------
// tf32 tensor-core GEMM: C[M][2048] = A[M][512] @ W[2048][512]^T + (b1 + b2)
//   A == nullptr -> A = g_h1 ; dst_sel: 0 -> g_E0, 1 -> g_xW1
// BM=128, BN=128, BK=32, 256 threads (8 warps as 2x4), mma m16n8k8 tf32.
// Double-buffered smem, stride 36 words (conflict-free fragment reads).
// ---------------------------------------------------------------------------
#define GSTR 36
#define GBUF (128 * GSTR)

__global__ __launch_bounds__(256) void gemm_tf32_kernel(
    const float* __restrict__ A_in,
    const float* __restrict__ W,
    const float* __restrict__ b1,
    const float* __restrict__ b2,
    int dst_sel, int M)
{
    const float* A = A_in ? A_in : g_h1;
    float* C = dst_sel ? g_xW1 : g_E0;

    extern __shared__ unsigned gsm[];
    unsigned* As = gsm;              // [2][128*36]
    unsigned* Bs = gsm + 2 * GBUF;   // [2][128*36]

    const int tid = threadIdx.x;
    const int lane = tid & 31;
    const int warp = tid >> 5;
    const int g = lane >> 2;
    const int tig = lane & 3;
    const int wm = warp & 1;         // 2 m-strips of 64
    const int wn = warp >> 1;        // 4 n-strips of 32
    const int m0 = blockIdx.y * 128;
    const int n0 = blockIdx.x * 128;

    float acc[4][4][4];
#pragma unroll
    for (int i = 0; i < 4; i++)
#pragma unroll
        for (int j = 0; j < 4; j++)
#pragma unroll
            for (int e = 0; e < 4; e++) acc[i][j][e] = 0.0f;

    // loader mapping: 1024 float4 per matrix per tile; 4 per thread
    int lrow[4], lc[4];
#pragma unroll
    for (int p = 0; p < 4; p++) {
        int id = tid + p * 256;
        lrow[p] = id >> 3;           // 0..127
        lc[p] = (id & 7) * 4;        // k within BK
    }

    // load tile 0 straight to smem buf 0
    {
#pragma unroll
        for (int p = 0; p < 4; p++) {
            int r = lrow[p], kc = lc[p];
            float4 va = make_float4(0.f, 0.f, 0.f, 0.f);
            if (m0 + r < M) va = *(const float4*)(A + (size_t)(m0 + r) * 512 + kc);
            unsigned* d = As + r * GSTR + kc;
            d[0] = f2tf(va.x); d[1] = f2tf(va.y); d[2] = f2tf(va.z); d[3] = f2tf(va.w);
            float4 vb = *(const float4*)(W + (size_t)(n0 + r) * 512 + kc);
            unsigned* e = Bs + r * GSTR + kc;
            e[0] = f2tf(vb.x); e[1] = f2tf(vb.y); e[2] = f2tf(vb.z); e[3] = f2tf(vb.w);
        }
    }
    __syncthreads();

    float4 pa[4], pb[4];
    for (int it = 0; it < 16; it++) {
        int buf = it & 1;
        if (it < 15) {
            int k0 = (it + 1) * 32;
#pragma unroll
            for (int p = 0; p < 4; p++) {
                int r = lrow[p], kc = lc[p];
                pa[p] = make_float4(0.f, 0.f, 0.f, 0.f);
                if (m0 + r < M) pa[p] = *(const float4*)(A + (size_t)(m0 + r) * 512 + k0 + kc);
                pb[p] = *(const float4*)(W + (size_t)(n0 + r) * 512 + k0 + kc);
            }
        }
        // compute on smem[buf]
        const unsigned* Ab = As + buf * GBUF;
        const unsigned* Bb = Bs + buf * GBUF;
#pragma unroll
        for (int kk = 0; kk < 4; kk++) {
            int kb = kk * 8;
            unsigned af[4][4];
#pragma unroll
            for (int mf = 0; mf < 4; mf++) {
                int r = wm * 64 + mf * 16 + g;
                af[mf][0] = Ab[r * GSTR + kb + tig];
                af[mf][1] = Ab[(r + 8) * GSTR + kb + tig];
                af[mf][2] = Ab[r * GSTR + kb + tig + 4];
                af[mf][3] = Ab[(r + 8) * GSTR + kb + tig + 4];
            }
            unsigned bf[4][2];
#pragma unroll
            for (int nf = 0; nf < 4; nf++) {
                int n = wn * 32 + nf * 8 + g;
                bf[nf][0] = Bb[n * GSTR + kb + tig];
                bf[nf][1] = Bb[n * GSTR + kb + tig + 4];
            }
#pragma unroll
            for (int mf = 0; mf < 4; mf++)
#pragma unroll
                for (int nf = 0; nf < 4; nf++)
                    mma_tf32(acc[mf][nf], af[mf], bf[nf]);
        }
        if (it < 15) {
            unsigned* Ad = As + (buf ^ 1) * GBUF;
            unsigned* Bd = Bs + (buf ^ 1) * GBUF;
#pragma unroll
            for (int p = 0; p < 4; p++) {
                int r = lrow[p], kc = lc[p];
                unsigned* d = Ad + r * GSTR + kc;
                d[0] = f2tf(pa[p].x); d[1] = f2tf(pa[p].y); d[2] = f2tf(pa[p].z); d[3] = f2tf(pa[p].w);
                unsigned* e = Bd + r * GSTR + kc;
                e[0] = f2tf(pb[p].x); e[1] = f2tf(pb[p].y); e[2] = f2tf(pb[p].z); e[3] = f2tf(pb[p].w);
            }
        }
        __syncthreads();
    }

    // epilogue: bias + store (float2 per c-pair)
#pragma unroll
    for (int nf = 0; nf < 4; nf++) {
        int n = n0 + wn * 32 + nf * 8 + 2 * tig;
        float bb0 = b1[n] + b2[n];
        float bb1 = b1[n + 1] + b2[n + 1];
#pragma unroll
        for (int mf = 0; mf < 4; mf++) {
            int r = m0 + wm * 64 + mf * 16 + g;
            if (r < M) {
                float2 v = make_float2(acc[mf][nf][0] + bb0, acc[mf][nf][1] + bb1);
                *(float2*)(C + (size_t)r * G4 + n) = v;
            }
            if (r + 8 < M) {
                float2 v = make_float2(acc[mf][nf][2] + bb0, acc[mf][nf][3] + bb1);
                *(float2*)(C + (size_t)(r + 8) * G4 + n) = v;
            }
        }
    }
}

// ---------------------------------------------------------------------------
// Persistent LSTM scan, tensor-core step GEMM.
// 128 blocks x 128 threads (1/SM). Block b owns 16 gate rows:
//   local row n (0..15) <-> Whh row (n&3)*512 + u0 + (n>>2),  u0 = 4*b.
// Warp w computes batches [16w,16w+16) x all 16 rows via tf32 mma (K=512).
// h ping-pongs through global in [batch][unit] layout, tf32-rounded.
// smem: sh_h [64][516] (A operand), sh_w [16][516] (B, loaded once),
//       gate_s [16][68] (mma out staging). 169.5 KB.
// ---------------------------------------------------------------------------
#define SHS 516
__global__ __launch_bounds__(SCAN_THREADS) void lstm_scan_kernel(
    const int* __restrict__ src,        // nullptr for layer 1
    const float* __restrict__ Whh,
    const int* __restrict__ sen_len,    // nullptr for layer 0
    float* __restrict__ final_out)      // nullptr for layer 0
{
    extern __shared__ unsigned ssm[];
    unsigned* sh_h = ssm;                          // [64][516] tf32 bits
    unsigned* sh_w = ssm + 64 * SHS;               // [16][516]
    float* gate_s = (float*)(ssm + 80 * SHS);      // [16][68]

    const int tid = threadIdx.x;
    const int lane = tid & 31;
    const int warp = tid >> 5;         // 0..3
    const int g = lane >> 2;
    const int tig = lane & 3;
    const int u0 = blockIdx.x * 4;
    const int b0 = lane, b1 = lane + 32;
    const int ug = warp;               // unit within block for cell phase
    const int mb = warp * 16;          // batch strip for mma

    // Load this block's 16 Whh rows into smem (tf32), once.
#pragma unroll
    for (int p = 0; p < 16; p++) {
        int id = tid + p * 128;        // 0..2047 float4s
        int n = id >> 7;               // 0..15
        int c4 = id & 127;
        int j = n >> 2, gt = n & 3;
        float4 v = *(const float4*)(Whh + (size_t)(gt * 512 + u0 + j) * 512 + c4 * 4);
        unsigned* d = sh_w + n * SHS + c4 * 4;
        d[0] = f2tf(v.x); d[1] = f2tf(v.y); d[2] = f2tf(v.z); d[3] = f2tf(v.w);
    }

    float c_0 = 0.0f, c_1 = 0.0f;
    int sl0 = -1, sl1 = -1;
    if (sen_len) { sl0 = sen_len[b0]; sl1 = sen_len[b1]; }

    for (int t = 0; t < T_LEN; t++) {
        // Stage h_prev ([batch][unit], already tf32 bits) into smem A operand.
        const float4* hsrc = (const float4*)g_hbuf[t & 1];
#pragma unroll 8
        for (int i = 0; i < 64; i++) {
            float4 v = __ldcg(hsrc + i * 128 + tid);
            *(float4*)(sh_h + i * SHS + tid * 4) = v;
        }
        __syncthreads();

        // Recurrent GEMM via mma: warp computes [16 batch x 16 rows], K=512.
        float acc0[4] = {0.f, 0.f, 0.f, 0.f};
        float acc1[4] = {0.f, 0.f, 0.f, 0.f};
        const unsigned* hA0 = sh_h + (mb + g) * SHS + tig;
        const unsigned* hA1 = hA0 + 8 * SHS;
        const unsigned* wB0 = sh_w + g * SHS + tig;
        const unsigned* wB1 = wB0 + 8 * SHS;
#pragma unroll 4
        for (int kk = 0; kk < 64; kk++) {
            unsigned a[4];
            a[0] = hA0[kk * 8];     a[1] = hA1[kk * 8];
            a[2] = hA0[kk * 8 + 4]; a[3] = hA1[kk * 8 + 4];
            unsigned bq0[2], bq1[2];
            bq0[0] = wB0[kk * 8]; bq0[1] = wB0[kk * 8 + 4];
            bq1[0] = wB1[kk * 8]; bq1[1] = wB1[kk * 8 + 4];
            mma_tf32(acc0, a, bq0);
            mma_tf32(acc1, a, bq1);
        }
        // stage mma outputs: gate_s[n][batch]
        gate_s[(2 * tig) * 68 + mb + g]         = acc0[0];
        gate_s[(2 * tig + 1) * 68 + mb + g]     = acc0[1];
        gate_s[(2 * tig) * 68 + mb + g + 8]     = acc0[2];
        gate_s[(2 * tig + 1) * 68 + mb + g + 8] = acc0[3];
        gate_s[(8 + 2 * tig) * 68 + mb + g]         = acc1[0];
        gate_s[(8 + 2 * tig + 1) * 68 + mb + g]     = acc1[1];
        gate_s[(8 + 2 * tig) * 68 + mb + g + 8]     = acc1[2];
        gate_s[(8 + 2 * tig + 1) * 68 + mb + g + 8] = acc1[3];
        __syncthreads();

        // Cell phase: thread handles unit u0+ug for batches b0, b1.
        float p0[4], p1[4];
        if (src) {
            int r0 = src[t * NBATCH + b0];
            int r1 = src[t * NBATCH + b1];
            const float* e0 = g_E0 + (size_t)r0 * G4 + u0 + ug;
            const float* e1 = g_E0 + (size_t)r1 * G4 + u0 + ug;
#pragma unroll
            for (int gt = 0; gt < 4; gt++) { p0[gt] = e0[gt * 512]; p1[gt] = e1[gt * 512]; }
        } else {
            const float* x0 = g_xW1 + (size_t)(t * NBATCH + b0) * G4 + u0 + ug;
            const float* x1 = g_xW1 + (size_t)(t * NBATCH + b1) * G4 + u0 + ug;
#pragma unroll
            for (int gt = 0; gt < 4; gt++) { p0[gt] = x0[gt * 512]; p1[gt] = x1[gt * 512]; }
        }
        float z0[4], z1[4];
#pragma unroll
        for (int gt = 0; gt < 4; gt++) {
            z0[gt] = gate_s[(ug * 4 + gt) * 68 + b0] + p0[gt];
            z1[gt] = gate_s[(ug * 4 + gt) * 68 + b1] + p1[gt];
        }

        float i0 = sigmoidf_(z0[0]);
        float f0 = sigmoidf_(z0[1]);
        float gg0 = tanhf(z0[2]);
        float o0 = sigmoidf_(z0[3]);
        c_0 = f0 * c_0 + i0 * gg0;
        float h0n = o0 * tanhf(c_0);

        float i1 = sigmoidf_(z1[0]);
        float f1 = sigmoidf_(z1[1]);
        float gg1 = tanhf(z1[2]);
        float o1 = sigmoidf_(z1[3]);
        c_1 = f1 * c_1 + i1 * gg1;
        float h1n = o1 * tanhf(c_1);

        int u = u0 + ug;
        float* hdst = g_hbuf[(t + 1) & 1];
        hdst[b0 * HID + u] = tf32f(h0n);
        hdst[b1 * HID + u] = tf32f(h1n);

        if (src) {
            g_h1[(size_t)(t * NBATCH + b0) * HID + u] = h0n;
            g_h1[(size_t)(t * NBATCH + b1) * HID + u] = h1n;
        } else {
            if (t == sl0 - 1) final_out[b0 * HID + u] = h0n;
            if (t == sl1 - 1) final_out[b1 * HID + u] = h1n;
        }

        // ---- grid barrier (flag + release) ----
        __threadfence();
        __syncthreads();
        unsigned want = (unsigned)(t + 1);
        if (blockIdx.x == 0) {
            if (tid > 0 && tid < SCAN_BLOCKS)
                while (ldvol(&g_flags[tid]) < want) {}
            __syncthreads();
            if (tid == 0) { __threadfence(); stvol(&g_release, want); }
        } else {
            if (tid == 0) {
                stvol(&g_flags[blockIdx.x], want);
                while (ldvol(&g_release) < want) {}
            }
            __syncthreads();
        }
        __threadfence();
    }
}

// ---------------------------------------------------------------------------
extern "C" void kernel_launch(void* const* d_in, const int* in_sizes, int n_in,
                              void* d_out, int out_size)
{
    const int*   src       = (const int*)  d_in[0];
    const int*   sen_len   = (const int*)  d_in[1];
    const float* emb_table = (const float*)d_in[2];
    const float* Wih0      = (const float*)d_in[3];
    const float* Whh0      = (const float*)d_in[4];
    const float* bih0      = (const float*)d_in[5];
    const float* bhh0      = (const float*)d_in[6];
    const float* Wih1      = (const float*)d_in[7];
    const float* Whh1      = (const float*)d_in[8];
    const float* bih1      = (const float*)d_in[9];
    const float* bhh1      = (const float*)d_in[10];
    float* out = (float*)d_out;

    const size_t gemm_smem = (size_t)4 * GBUF * sizeof(unsigned);        // 73728 B
    const size_t scan_smem = (size_t)(80 * SHS + 16 * 68) * sizeof(float); // 169472 B
    cudaFuncSetAttribute(gemm_tf32_kernel,
                         cudaFuncAttributeMaxDynamicSharedMemorySize, (int)gemm_smem);
    cudaFuncSetAttribute(lstm_scan_kernel,
                         cudaFuncAttributeMaxDynamicSharedMemorySize, (int)scan_smem);

    // Phase 0: E0 = emb_table @ Wih0^T + b0   (10000 x 2048)
    {
        dim3 grid(G4 / 128, (NVOCAB + 127) / 128);
        gemm_tf32_kernel<<<grid, 256, gemm_smem>>>(emb_table, Wih0, bih0, bhh0, 0, NVOCAB);
    }

    // Phase 1: layer-0 scan
    zero_init_kernel<<<64, 512>>>();
    lstm_scan_kernel<<<SCAN_BLOCKS, SCAN_THREADS, scan_smem>>>(
        src, Whh0, nullptr, nullptr);

    // Phase 2: xW1 = h1 @ Wih1^T + b1   (32768 x 2048)
    {
        dim3 grid(G4 / 128, (T_LEN * NBATCH) / 128);
        gemm_tf32_kernel<<<grid, 256, gemm_smem>>>(nullptr, Wih1, bih1, bhh1, 1,
                                                   T_LEN * NBATCH);
    }

    // Phase 3: layer-1 scan (+ final gather at sen_len-1)
    zero_init_kernel<<<64, 512>>>();
    lstm_scan_kernel<<<SCAN_BLOCKS, SCAN_THREADS, scan_smem>>>(
        nullptr, Whh1, sen_len, out);
}

// round 4
// speedup vs baseline: 3.6583x; 2.5196x over previous
#include <cuda_runtime.h>
#include <math.h>
#include <stdint.h>

// Problem constants
#define T_LEN 512
#define NBATCH 64
#define HID 512
#define G4 2048          // 4*HID
#define NVOCAB 10000

#define SCAN_BLOCKS 128
#define SCAN_THREADS 128
#define RPAD 20          // red buffer row pad (floats)

// -------- device scratch --------
__device__ float g_E0[(size_t)NVOCAB * G4];            // emb @ Wih0^T + b0, [vocab][2048]
__device__ float g_h1[(size_t)T_LEN * NBATCH * HID];   // layer0 outputs [t*64+b][u]
__device__ float g_xW1[(size_t)T_LEN * G4 * NBATCH];   // h1 @ Wih1^T + b1, [t][r][b] (transposed!)
__device__ float g_hbuf[2][NBATCH * HID];              // ping-pong h, PERMUTED fragment layout
__device__ unsigned g_flags[SCAN_BLOCKS];
__device__ unsigned g_release;

// ---------------- helpers ----------------
__device__ __forceinline__ unsigned f2tf(float f) {
    unsigned r; asm("cvt.rna.tf32.f32 %0, %1;" : "=r"(r) : "f"(f)); return r;
}
__device__ __forceinline__ void mma_tf32(float* c, const unsigned* a, const unsigned* b) {
    asm("mma.sync.aligned.m16n8k8.row.col.f32.tf32.tf32.f32 "
        "{%0,%1,%2,%3}, {%4,%5,%6,%7}, {%8,%9}, {%0,%1,%2,%3};"
        : "+f"(c[0]), "+f"(c[1]), "+f"(c[2]), "+f"(c[3])
        : "r"(a[0]), "r"(a[1]), "r"(a[2]), "r"(a[3]), "r"(b[0]), "r"(b[1]));
}
__device__ __forceinline__ unsigned ld_acq(const unsigned* p) {
    unsigned v; asm volatile("ld.acquire.gpu.global.u32 %0, [%1];" : "=r"(v) : "l"(p)); return v;
}
__device__ __forceinline__ void st_rel(unsigned* p, unsigned v) {
    asm volatile("st.release.gpu.global.u32 [%0], %1;" :: "l"(p), "r"(v));
}
__device__ __forceinline__ void cp16(unsigned sdst, const void* gsrc) {
    asm volatile("cp.async.cg.shared.global [%0], [%1], 16;" :: "r"(sdst), "l"(gsrc));
}
__device__ __forceinline__ float tanh_ap(float x) {
    float y; asm("tanh.approx.f32 %0, %1;" : "=f"(y) : "f"(x)); return y;
}
__device__ __forceinline__ float sig_(float x) {
    return __fdividef(1.0f, 1.0f + __expf(-x));
}
// permuted index for h value (batch b, unit k): matches mma A-fragment layout
__device__ __forceinline__ int pidx(int b, int k) {
    return (((k >> 3) * 4 + ((b >> 4) & 3)) * 32 + ((b & 7) * 4 + (k & 3))) * 4
           + ((b >> 3) & 1) + 2 * ((k >> 2) & 1);
}

// ---------------------------------------------------------------------------
__global__ void zero_init_kernel() {
    int i = blockIdx.x * blockDim.x + threadIdx.x;
    if (i < HID * NBATCH) ((float*)g_hbuf)[i] = 0.0f;   // g_hbuf[0]
    if (i < SCAN_BLOCKS) g_flags[i] = 0u;
    if (i == 0) g_release = 0u;
}

// ---------------------------------------------------------------------------
// tf32 tensor-core GEMM: C = A[M][512] @ W[2048][512]^T + (b1+b2)
//   dst_sel 0: C = g_E0, layout [m][2048]
//   dst_sel 1: C = g_xW1, layout [t][r][b] with m = t*64+b  (transposed epilogue)
// ---------------------------------------------------------------------------
#define GSTR 36
#define GBUF (128 * GSTR)

__global__ __launch_bounds__(256) void gemm_tf32_kernel(
    const float* __restrict__ A_in,
    const float* __restrict__ W,
    const float* __restrict__ bi1,
    const float* __restrict__ bi2,
    int dst_sel, int M)
{
    const float* A = A_in ? A_in : g_h1;
    float* C = dst_sel ? g_xW1 : g_E0;

    extern __shared__ unsigned gsm[];
    unsigned* As = gsm;
    unsigned* Bs = gsm + 2 * GBUF;

    const int tid = threadIdx.x;
    const int lane = tid & 31;
    const int warp = tid >> 5;
    const int g = lane >> 2;
    const int tig = lane & 3;
    const int wm = warp & 1;
    const int wn = warp >> 1;
    const int m0 = blockIdx.y * 128;
    const int n0 = blockIdx.x * 128;

    float acc[4][4][4];
#pragma unroll
    for (int i = 0; i < 4; i++)
#pragma unroll
        for (int j = 0; j < 4; j++)
#pragma unroll
            for (int e = 0; e < 4; e++) acc[i][j][e] = 0.0f;

    int lrow[4], lc[4];
#pragma unroll
    for (int p = 0; p < 4; p++) {
        int id = tid + p * 256;
        lrow[p] = id >> 3;
        lc[p] = (id & 7) * 4;
    }

    {
#pragma unroll
        for (int p = 0; p < 4; p++) {
            int r = lrow[p], kc = lc[p];
            float4 va = make_float4(0.f, 0.f, 0.f, 0.f);
            if (m0 + r < M) va = *(const float4*)(A + (size_t)(m0 + r) * 512 + kc);
            unsigned* d = As + r * GSTR + kc;
            d[0] = f2tf(va.x); d[1] = f2tf(va.y); d[2] = f2tf(va.z); d[3] = f2tf(va.w);
            float4 vb = *(const float4*)(W + (size_t)(n0 + r) * 512 + kc);
            unsigned* e = Bs + r * GSTR + kc;
            e[0] = f2tf(vb.x); e[1] = f2tf(vb.y); e[2] = f2tf(vb.z); e[3] = f2tf(vb.w);
        }
    }
    __syncthreads();

    float4 pa[4], pb[4];
    for (int it = 0; it < 16; it++) {
        int buf = it & 1;
        if (it < 15) {
            int k0 = (it + 1) * 32;
#pragma unroll
            for (int p = 0; p < 4; p++) {
                int r = lrow[p], kc = lc[p];
                pa[p] = make_float4(0.f, 0.f, 0.f, 0.f);
                if (m0 + r < M) pa[p] = *(const float4*)(A + (size_t)(m0 + r) * 512 + k0 + kc);
                pb[p] = *(const float4*)(W + (size_t)(n0 + r) * 512 + k0 + kc);
            }
        }
        const unsigned* Ab = As + buf * GBUF;
        const unsigned* Bb = Bs + buf * GBUF;
#pragma unroll
        for (int kk = 0; kk < 4; kk++) {
            int kb = kk * 8;
            unsigned af[4][4];
#pragma unroll
            for (int mf = 0; mf < 4; mf++) {
                int r = wm * 64 + mf * 16 + g;
                af[mf][0] = Ab[r * GSTR + kb + tig];
                af[mf][1] = Ab[(r + 8) * GSTR + kb + tig];
                af[mf][2] = Ab[r * GSTR + kb + tig + 4];
                af[mf][3] = Ab[(r + 8) * GSTR + kb + tig + 4];
            }
            unsigned bf[4][2];
#pragma unroll
            for (int nf = 0; nf < 4; nf++) {
                int n = wn * 32 + nf * 8 + g;
                bf[nf][0] = Bb[n * GSTR + kb + tig];
                bf[nf][1] = Bb[n * GSTR + kb + tig + 4];
            }
#pragma unroll
            for (int mf = 0; mf < 4; mf++)
#pragma unroll
                for (int nf = 0; nf < 4; nf++)
                    mma_tf32(acc[mf][nf], af[mf], bf[nf]);
        }
        if (it < 15) {
            unsigned* Ad = As + (buf ^ 1) * GBUF;
            unsigned* Bd = Bs + (buf ^ 1) * GBUF;
#pragma unroll
            for (int p = 0; p < 4; p++) {
                int r = lrow[p], kc = lc[p];
                unsigned* d = Ad + r * GSTR + kc;
                d[0] = f2tf(pa[p].x); d[1] = f2tf(pa[p].y); d[2] = f2tf(pa[p].z); d[3] = f2tf(pa[p].w);
                unsigned* e = Bd + r * GSTR + kc;
                e[0] = f2tf(pb[p].x); e[1] = f2tf(pb[p].y); e[2] = f2tf(pb[p].z); e[3] = f2tf(pb[p].w);
            }
        }
        __syncthreads();
    }

    if (dst_sel) {
        // transposed store: C[t][n][b], m = t*64 + b  (M = 32768, exact tiling)
#pragma unroll
        for (int nf = 0; nf < 4; nf++) {
            int n = n0 + wn * 32 + nf * 8 + 2 * tig;
            float bb0 = bi1[n] + bi2[n];
            float bb1 = bi1[n + 1] + bi2[n + 1];
#pragma unroll
            for (int mf = 0; mf < 4; mf++) {
                int m = m0 + wm * 64 + mf * 16 + g;
                size_t base1 = (size_t)(m >> 6) * (G4 * 64) + (size_t)n * 64 + (m & 63);
                C[base1]      = acc[mf][nf][0] + bb0;
                C[base1 + 64] = acc[mf][nf][1] + bb1;
                int m2 = m + 8;
                size_t base2 = (size_t)(m2 >> 6) * (G4 * 64) + (size_t)n * 64 + (m2 & 63);
                C[base2]      = acc[mf][nf][2] + bb0;
                C[base2 + 64] = acc[mf][nf][3] + bb1;
            }
        }
    } else {
#pragma unroll
        for (int nf = 0; nf < 4; nf++) {
            int n = n0 + wn * 32 + nf * 8 + 2 * tig;
            float bb0 = bi1[n] + bi2[n];
            float bb1 = bi1[n + 1] + bi2[n + 1];
#pragma unroll
            for (int mf = 0; mf < 4; mf++) {
                int r = m0 + wm * 64 + mf * 16 + g;
                if (r < M) {
                    float2 v = make_float2(acc[mf][nf][0] + bb0, acc[mf][nf][1] + bb1);
                    *(float2*)(C + (size_t)r * G4 + n) = v;
                }
                if (r + 8 < M) {
                    float2 v = make_float2(acc[mf][nf][2] + bb0, acc[mf][nf][3] + bb1);
                    *(float2*)(C + (size_t)(r + 8) * G4 + n) = v;
                }
            }
        }
    }
}

// ---------------------------------------------------------------------------
// Persistent LSTM scan. 128 blocks x 128 threads (1/SM). Block owns 16 gate
// rows (4 units x 4 gates): local row n <-> Whh[(n&3)*512 + u0 + (n>>2)].
// Warp w owns K-slice [128w,128w+128): computes m64 x n16 x k128 partials.
//   - B fragments: 64 registers, loaded ONCE per scan.
//   - A (h) fragments: permuted layout in g_hbuf; warp cp.asyncs its own
//     8KB k-slice into smem, fragment = 1 conflict-free LDS.128.
//   - K-partials reduced via smem straight into the cell phase.
// ---------------------------------------------------------------------------
__global__ __launch_bounds__(SCAN_THREADS) void lstm_scan_kernel(
    const int* __restrict__ src,        // nullptr for layer 1
    const float* __restrict__ Whh,
    const int* __restrict__ sen_len,    // nullptr for layer 0
    float* __restrict__ final_out)      // nullptr for layer 0
{
    extern __shared__ unsigned ssm[];
    unsigned* sh_h = ssm;                      // 32768 words, permuted h
    float* red = (float*)(ssm + 32768);        // [4][64][RPAD]

    const int tid = threadIdx.x;
    const int lane = tid & 31;
    const int warp = tid >> 5;       // 0..3 = k-slice
    const int g = lane >> 2;
    const int tig = lane & 3;
    const int u0 = blockIdx.x * 4;
    const int b0 = lane, b1 = lane + 32;
    const int ug = warp;             // unit handled in cell phase

    unsigned sh_base;
    asm("{ .reg .u64 t; cvta.to.shared.u64 t, %1; cvt.u32.u64 %0, t; }"
        : "=r"(sh_base) : "l"(sh_h));

    // ---- B fragments in registers (once per scan) ----
    unsigned breg[16][2][2];
#pragma unroll
    for (int kkl = 0; kkl < 16; kkl++) {
#pragma unroll
        for (int nt = 0; nt < 2; nt++) {
            int n = nt * 8 + g;
            int row = (n & 3) * 512 + u0 + (n >> 2);
            const float* wr = Whh + (size_t)row * 512 + warp * 128 + kkl * 8 + tig;
            breg[kkl][nt][0] = f2tf(wr[0]);
            breg[kkl][nt][1] = f2tf(wr[4]);
        }
    }

    float c_0 = 0.0f, c_1 = 0.0f;
    int sl0 = -1, sl1 = -1;
    if (sen_len) { sl0 = sen_len[b0]; sl1 = sen_len[b1]; }

    for (int t = 0; t < T_LEN; t++) {
        // ---- prefetch cell inputs (independent of h) ----
        float p0[4], p1[4];
        if (src) {
            int r0 = src[t * NBATCH + b0];
            int r1 = src[t * NBATCH + b1];
            const float* e0 = g_E0 + (size_t)r0 * G4 + u0 + ug;
            const float* e1 = g_E0 + (size_t)r1 * G4 + u0 + ug;
#pragma unroll
            for (int gt = 0; gt < 4; gt++) { p0[gt] = e0[gt * 512]; p1[gt] = e1[gt * 512]; }
        } else {
            const float* xb = g_xW1 + (size_t)t * (G4 * 64) + (size_t)(u0 + ug) * 64;
#pragma unroll
            for (int gt = 0; gt < 4; gt++) {
                p0[gt] = xb[gt * 32768 + b0];
                p1[gt] = xb[gt * 32768 + b1];
            }
        }

        // ---- stage this warp's k-slice of h (8 KB) via cp.async ----
        // warp slice: float4s [warp*2048, warp*2048+2048); per iter: 32 lanes
        // x 16B = 512B, so smem stride is i*512 bytes.
        {
            const float4* hs = (const float4*)(g_hbuf[t & 1]) + warp * 2048 + lane;
            unsigned sd = sh_base + (unsigned)(warp * 32768 + lane * 16);
#pragma unroll 8
            for (int i = 0; i < 64; i++)
                cp16(sd + i * 512, hs + i * 32);
            asm volatile("cp.async.commit_group;");
            asm volatile("cp.async.wait_group 0;" ::: "memory");
            __syncwarp();
        }

        // ---- mma: m64 x n16 x k128 partial ----
        float acc[4][2][4];
#pragma unroll
        for (int mt = 0; mt < 4; mt++)
#pragma unroll
            for (int nt = 0; nt < 2; nt++)
#pragma unroll
                for (int e = 0; e < 4; e++) acc[mt][nt][e] = 0.0f;

#pragma unroll
        for (int kkl = 0; kkl < 16; kkl++) {
            int kkg = warp * 16 + kkl;
#pragma unroll
            for (int mt = 0; mt < 4; mt++) {
                uint4 a = *(const uint4*)(sh_h + ((kkg * 4 + mt) * 32 + lane) * 4);
                mma_tf32(acc[mt][0], (const unsigned*)&a, breg[kkl][0]);
                mma_tf32(acc[mt][1], (const unsigned*)&a, breg[kkl][1]);
            }
        }

        // ---- store partials: red[w][b][n] ----
#pragma unroll
        for (int mt = 0; mt < 4; mt++)
#pragma unroll
            for (int nt = 0; nt < 2; nt++) {
                int bb = mt * 16 + g;
                float* rp = &red[(warp * 64 + bb) * RPAD + nt * 8 + 2 * tig];
                *(float2*)rp = make_float2(acc[mt][nt][0], acc[mt][nt][1]);
                *(float2*)(rp + 8 * RPAD) = make_float2(acc[mt][nt][2], acc[mt][nt][3]);
            }
        __syncthreads();

        // ---- cell phase: reduce k-partials + activations ----
        float z0[4], z1[4];
#pragma unroll
        for (int gt = 0; gt < 4; gt++) { z0[gt] = p0[gt]; z1[gt] = p1[gt]; }
#pragma unroll
        for (int w = 0; w < 4; w++) {
            float4 v0 = *(const float4*)&red[(w * 64 + b0) * RPAD + ug * 4];
            float4 v1 = *(const float4*)&red[(w * 64 + b1) * RPAD + ug * 4];
            z0[0] += v0.x; z0[1] += v0.y; z0[2] += v0.z; z0[3] += v0.w;
            z1[0] += v1.x; z1[1] += v1.y; z1[2] += v1.z; z1[3] += v1.w;
        }

        float i0 = sig_(z0[0]), f0 = sig_(z0[1]), gg0 = tanh_ap(z0[2]), o0 = sig_(z0[3]);
        c_0 = f0 * c_0 + i0 * gg0;
        float h0n = o0 * tanh_ap(c_0);

        float i1 = sig_(z1[0]), f1 = sig_(z1[1]), gg1 = tanh_ap(z1[2]), o1 = sig_(z1[3]);
        c_1 = f1 * c_1 + i1 * gg1;
        float h1n = o1 * tanh_ap(c_1);

        int u = u0 + ug;
        float* hd = g_hbuf[(t + 1) & 1];
        hd[pidx(b0, u)] = __uint_as_float(f2tf(h0n));
        hd[pidx(b1, u)] = __uint_as_float(f2tf(h1n));

        if (src) {
            g_h1[(size_t)(t * NBATCH + b0) * HID + u] = h0n;
            g_h1[(size_t)(t * NBATCH + b1) * HID + u] = h1n;
        } else {
            if (t == sl0 - 1) final_out[b0 * HID + u] = h0n;
            if (t == sl1 - 1) final_out[b1 * HID + u] = h1n;
        }

        // ---- grid barrier (acquire/release, flag + broadcast) ----
        __syncthreads();   // all h writes in block issued
        unsigned want = (unsigned)(t + 1);
        if (blockIdx.x == 0) {
            if (tid > 0 && tid < SCAN_BLOCKS)
                while (ld_acq(&g_flags[tid]) < want) { }
            __syncthreads();
            if (tid == 0) st_rel(&g_release, want);
        } else {
            if (tid == 0) {
                st_rel(&g_flags[blockIdx.x], want);
                while (ld_acq(&g_release) < want) { }
            }
            __syncthreads();
        }
    }
}

// ---------------------------------------------------------------------------
extern "C" void kernel_launch(void* const* d_in, const int* in_sizes, int n_in,
                              void* d_out, int out_size)
{
    const int*   src       = (const int*)  d_in[0];
    const int*   sen_len   = (const int*)  d_in[1];
    const float* emb_table = (const float*)d_in[2];
    const float* Wih0      = (const float*)d_in[3];
    const float* Whh0      = (const float*)d_in[4];
    const float* bih0      = (const float*)d_in[5];
    const float* bhh0      = (const float*)d_in[6];
    const float* Wih1      = (const float*)d_in[7];
    const float* Whh1      = (const float*)d_in[8];
    const float* bih1      = (const float*)d_in[9];
    const float* bhh1      = (const float*)d_in[10];
    float* out = (float*)d_out;

    const size_t gemm_smem = (size_t)4 * GBUF * sizeof(unsigned);           // 73728 B
    const size_t scan_smem = (size_t)(32768 + 4 * 64 * RPAD) * sizeof(float); // 151552 B
    cudaFuncSetAttribute(gemm_tf32_kernel,
                         cudaFuncAttributeMaxDynamicSharedMemorySize, (int)gemm_smem);
    cudaFuncSetAttribute(lstm_scan_kernel,
                         cudaFuncAttributeMaxDynamicSharedMemorySize, (int)scan_smem);

    // Phase 0: E0 = emb_table @ Wih0^T + b0   (10000 x 2048)
    {
        dim3 grid(G4 / 128, (NVOCAB + 127) / 128);
        gemm_tf32_kernel<<<grid, 256, gemm_smem>>>(emb_table, Wih0, bih0, bhh0, 0, NVOCAB);
    }

    // Phase 1: layer-0 scan
    zero_init_kernel<<<64, 512>>>();
    lstm_scan_kernel<<<SCAN_BLOCKS, SCAN_THREADS, scan_smem>>>(
        src, Whh0, nullptr, nullptr);

    // Phase 2: xW1 = h1 @ Wih1^T + b1  -> transposed [t][r][b]
    {
        dim3 grid(G4 / 128, (T_LEN * NBATCH) / 128);
        gemm_tf32_kernel<<<grid, 256, gemm_smem>>>(nullptr, Wih1, bih1, bhh1, 1,
                                                   T_LEN * NBATCH);
    }

    // Phase 3: layer-1 scan (+ final gather at sen_len-1)
    zero_init_kernel<<<64, 512>>>();
    lstm_scan_kernel<<<SCAN_BLOCKS, SCAN_THREADS, scan_smem>>>(
        nullptr, Whh1, sen_len, out);
}

// round 6
// speedup vs baseline: 5.4816x; 1.4984x over previous
#include <cuda_runtime.h>
#include <cuda_fp16.h>
#include <math.h>
#include <stdint.h>

// Problem constants
#define T_LEN 512
#define NBATCH 64
#define HID 512
#define G4 2048          // 4*HID
#define NVOCAB 10000

#define SCAN_BLOCKS 128
#define SCAN_THREADS 128
#define RPAD 20          // red buffer row pad (floats)

// -------- device scratch --------
__device__ float g_E0[(size_t)NVOCAB * G4];            // emb @ Wih0^T + b0, [vocab][2048]
__device__ float g_h1[(size_t)T_LEN * NBATCH * HID];   // layer0 outputs [t*64+b][u]
__device__ float g_xW1[(size_t)T_LEN * G4 * NBATCH];   // h1 @ Wih1^T + b1, [t][r][b]
__device__ __align__(16) __half g_hbuf16[2][NBATCH * HID]; // ping-pong h, fp16 fragment layout
__device__ unsigned g_ctr;                             // barrier counter (monotonic)

// ---------------- helpers ----------------
__device__ __forceinline__ void mma_tf32(float* c, const unsigned* a, const unsigned* b) {
    asm("mma.sync.aligned.m16n8k8.row.col.f32.tf32.tf32.f32 "
        "{%0,%1,%2,%3}, {%4,%5,%6,%7}, {%8,%9}, {%0,%1,%2,%3};"
        : "+f"(c[0]), "+f"(c[1]), "+f"(c[2]), "+f"(c[3])
        : "r"(a[0]), "r"(a[1]), "r"(a[2]), "r"(a[3]), "r"(b[0]), "r"(b[1]));
}
__device__ __forceinline__ void mma_f16(float* c, const unsigned* a, const unsigned* b) {
    asm("mma.sync.aligned.m16n8k16.row.col.f32.f16.f16.f32 "
        "{%0,%1,%2,%3}, {%4,%5,%6,%7}, {%8,%9}, {%0,%1,%2,%3};"
        : "+f"(c[0]), "+f"(c[1]), "+f"(c[2]), "+f"(c[3])
        : "r"(a[0]), "r"(a[1]), "r"(a[2]), "r"(a[3]), "r"(b[0]), "r"(b[1]));
}
__device__ __forceinline__ unsigned ld_acq(const unsigned* p) {
    unsigned v; asm volatile("ld.acquire.gpu.global.u32 %0, [%1];" : "=r"(v) : "l"(p)); return v;
}
__device__ __forceinline__ void cp16(unsigned sdst, const void* gsrc) {
    asm volatile("cp.async.cg.shared.global [%0], [%1], 16;" :: "r"(sdst), "l"(gsrc));
}
__device__ __forceinline__ float tanh_ap(float x) {
    float y; asm("tanh.approx.f32 %0, %1;" : "=f"(y) : "f"(x)); return y;
}
__device__ __forceinline__ float sig_(float x) {
    return __fdividef(1.0f, 1.0f + __expf(-x));
}
// fp16 half-index for h value (batch b, unit k) in m16n8k16 A-fragment layout.
// uint4 tile index = (k/16)*4 + b/16; lane = (b%8)*4 + ((k%8)/2);
// word = 2*(k%16>=8) + (b%16>=8); half = k&1.
__device__ __forceinline__ int hidx16(int b, int k) {
    int kk = k >> 4, mt = b >> 4, r = b & 15, kl = k & 15;
    int lane = (r & 7) * 4 + ((kl & 7) >> 1);
    int w = ((kl >> 3) << 1) | (r >> 3);
    return (((kk * 4 + mt) * 32 + lane) * 4 + w) * 2 + (k & 1);
}

// ---------------------------------------------------------------------------
__global__ void zero_init_kernel() {
    int i = blockIdx.x * blockDim.x + threadIdx.x;
    if (i < (NBATCH * HID) / 2) ((unsigned*)g_hbuf16)[i] = 0u;  // g_hbuf16[0]
    if (i == 0) g_ctr = 0u;
}

// ---------------------------------------------------------------------------
// tf32 tensor-core GEMM: C = A[M][512] @ W[2048][512]^T + (b1+b2)
//   dst_sel 0: C = g_E0, layout [m][2048]
//   dst_sel 1: C = g_xW1, layout [t][r][b], m = t*64+b
// Stagers feed raw fp32 bits to HMMA.TF32 (HW truncates mantissa).
// ---------------------------------------------------------------------------
#define GSTR 36
#define GBUF (128 * GSTR)

__global__ __launch_bounds__(256) void gemm_tf32_kernel(
    const float* __restrict__ A_in,
    const float* __restrict__ W,
    const float* __restrict__ bi1,
    const float* __restrict__ bi2,
    int dst_sel, int M)
{
    const float* A = A_in ? A_in : g_h1;
    float* C = dst_sel ? g_xW1 : g_E0;

    extern __shared__ unsigned gsm[];
    unsigned* As = gsm;
    unsigned* Bs = gsm + 2 * GBUF;

    const int tid = threadIdx.x;
    const int lane = tid & 31;
    const int warp = tid >> 5;
    const int g = lane >> 2;
    const int tig = lane & 3;
    const int wm = warp & 1;
    const int wn = warp >> 1;
    const int m0 = blockIdx.y * 128;
    const int n0 = blockIdx.x * 128;

    float acc[4][4][4];
#pragma unroll
    for (int i = 0; i < 4; i++)
#pragma unroll
        for (int j = 0; j < 4; j++)
#pragma unroll
            for (int e = 0; e < 4; e++) acc[i][j][e] = 0.0f;

    int lrow[4], lc[4];
#pragma unroll
    for (int p = 0; p < 4; p++) {
        int id = tid + p * 256;
        lrow[p] = id >> 3;
        lc[p] = (id & 7) * 4;
    }

    {
#pragma unroll
        for (int p = 0; p < 4; p++) {
            int r = lrow[p], kc = lc[p];
            float4 va = make_float4(0.f, 0.f, 0.f, 0.f);
            if (m0 + r < M) va = *(const float4*)(A + (size_t)(m0 + r) * 512 + kc);
            *(uint4*)(As + r * GSTR + kc) = *(const uint4*)&va;
            float4 vb = *(const float4*)(W + (size_t)(n0 + r) * 512 + kc);
            *(uint4*)(Bs + r * GSTR + kc) = *(const uint4*)&vb;
        }
    }
    __syncthreads();

    float4 pa[4], pb[4];
    for (int it = 0; it < 16; it++) {
        int buf = it & 1;
        if (it < 15) {
            int k0 = (it + 1) * 32;
#pragma unroll
            for (int p = 0; p < 4; p++) {
                int r = lrow[p], kc = lc[p];
                pa[p] = make_float4(0.f, 0.f, 0.f, 0.f);
                if (m0 + r < M) pa[p] = *(const float4*)(A + (size_t)(m0 + r) * 512 + k0 + kc);
                pb[p] = *(const float4*)(W + (size_t)(n0 + r) * 512 + k0 + kc);
            }
        }
        const unsigned* Ab = As + buf * GBUF;
        const unsigned* Bb = Bs + buf * GBUF;
#pragma unroll
        for (int kk = 0; kk < 4; kk++) {
            int kb = kk * 8;
            unsigned af[4][4];
#pragma unroll
            for (int mf = 0; mf < 4; mf++) {
                int r = wm * 64 + mf * 16 + g;
                af[mf][0] = Ab[r * GSTR + kb + tig];
                af[mf][1] = Ab[(r + 8) * GSTR + kb + tig];
                af[mf][2] = Ab[r * GSTR + kb + tig + 4];
                af[mf][3] = Ab[(r + 8) * GSTR + kb + tig + 4];
            }
            unsigned bf[4][2];
#pragma unroll
            for (int nf = 0; nf < 4; nf++) {
                int n = wn * 32 + nf * 8 + g;
                bf[nf][0] = Bb[n * GSTR + kb + tig];
                bf[nf][1] = Bb[n * GSTR + kb + tig + 4];
            }
#pragma unroll
            for (int mf = 0; mf < 4; mf++)
#pragma unroll
                for (int nf = 0; nf < 4; nf++)
                    mma_tf32(acc[mf][nf], af[mf], bf[nf]);
        }
        if (it < 15) {
            unsigned* Ad = As + (buf ^ 1) * GBUF;
            unsigned* Bd = Bs + (buf ^ 1) * GBUF;
#pragma unroll
            for (int p = 0; p < 4; p++) {
                int r = lrow[p], kc = lc[p];
                *(uint4*)(Ad + r * GSTR + kc) = *(const uint4*)&pa[p];
                *(uint4*)(Bd + r * GSTR + kc) = *(const uint4*)&pb[p];
            }
        }
        __syncthreads();
    }

    if (dst_sel) {
#pragma unroll
        for (int nf = 0; nf < 4; nf++) {
            int n = n0 + wn * 32 + nf * 8 + 2 * tig;
            float bb0 = bi1[n] + bi2[n];
            float bb1 = bi1[n + 1] + bi2[n + 1];
#pragma unroll
            for (int mf = 0; mf < 4; mf++) {
                int m = m0 + wm * 64 + mf * 16 + g;
                size_t base1 = (size_t)(m >> 6) * (G4 * 64) + (size_t)n * 64 + (m & 63);
                C[base1]      = acc[mf][nf][0] + bb0;
                C[base1 + 64] = acc[mf][nf][1] + bb1;
                int m2 = m + 8;
                size_t base2 = (size_t)(m2 >> 6) * (G4 * 64) + (size_t)n * 64 + (m2 & 63);
                C[base2]      = acc[mf][nf][2] + bb0;
                C[base2 + 64] = acc[mf][nf][3] + bb1;
            }
        }
    } else {
#pragma unroll
        for (int nf = 0; nf < 4; nf++) {
            int n = n0 + wn * 32 + nf * 8 + 2 * tig;
            float bb0 = bi1[n] + bi2[n];
            float bb1 = bi1[n + 1] + bi2[n + 1];
#pragma unroll
            for (int mf = 0; mf < 4; mf++) {
                int r = m0 + wm * 64 + mf * 16 + g;
                if (r < M) {
                    float2 v = make_float2(acc[mf][nf][0] + bb0, acc[mf][nf][1] + bb1);
                    *(float2*)(C + (size_t)r * G4 + n) = v;
                }
                if (r + 8 < M) {
                    float2 v = make_float2(acc[mf][nf][2] + bb0, acc[mf][nf][3] + bb1);
                    *(float2*)(C + (size_t)(r + 8) * G4 + n) = v;
                }
            }
        }
    }
}

// ---------------------------------------------------------------------------
// Persistent LSTM scan, fp16 h state + m16n8k16 f16 mma (fp32 accumulate).
// 128 CTAs x 128 threads, flat launch (1/SM, proven co-resident).
// Block owns 16 gate rows (4 units): local row n <-> Whh[(n&3)*512+u0+(n>>2)].
// Warp w owns K-slice [128w,128w+128): m64(batch) x n16(rows) x k128.
//   - B (Whh) fp16 fragments: 32 registers, loaded once per scan.
//   - A (h) fp16 fragments: permuted layout in g_hbuf16; warp cp.asyncs its
//     16KB slice; one uint4 LDS = one A fragment.
//   - K-partials reduced via smem red into the cell phase.
//   - grid barrier: red.release.gpu on one counter + acquire-poll.
// ---------------------------------------------------------------------------
__global__ __launch_bounds__(SCAN_THREADS) void lstm_scan_kernel(
    const int* __restrict__ src,        // nullptr for layer 1
    const float* __restrict__ Whh,
    const int* __restrict__ sen_len,    // nullptr for layer 0
    float* __restrict__ final_out)      // nullptr for layer 0
{
    extern __shared__ unsigned ssm[];
    unsigned* sh_h = ssm;                          // 16384 u32 = 64KB fp16 h
    float* red = (float*)(ssm + 16384);            // [4][64][RPAD]
    float* hex = (float*)(ssm + 16384 + 4 * 64 * RPAD);  // [4][64]

    const int tid = threadIdx.x;
    const int lane = tid & 31;
    const int warp = tid >> 5;       // 0..3 = k-slice
    const int g = lane >> 2;
    const int tig = lane & 3;
    const int u0 = blockIdx.x * 4;
    const int b0 = lane, b1 = lane + 32;
    const int ug = warp;             // unit handled in cell phase
    const unsigned nblk = gridDim.x;

    unsigned sh_base;
    asm("{ .reg .u64 t; cvta.to.shared.u64 t, %1; cvt.u32.u64 %0, t; }"
        : "=r"(sh_base) : "l"((void*)ssm));

    // ---- B (Whh) fp16 fragments in registers, once per scan ----
    // breg[kkl][nt]: k-chunk kkl (16 k), n-tile nt (rows nt*8+g).
    unsigned breg[8][2][2];
#pragma unroll
    for (int kkl = 0; kkl < 8; kkl++) {
#pragma unroll
        for (int nt = 0; nt < 2; nt++) {
            int n = nt * 8 + g;
            int row = (n & 3) * 512 + u0 + (n >> 2);
            const float* wr = Whh + (size_t)row * 512 + warp * 128 + kkl * 16;
            __half2 h0 = __floats2half2_rn(wr[2 * tig], wr[2 * tig + 1]);
            __half2 h1 = __floats2half2_rn(wr[2 * tig + 8], wr[2 * tig + 9]);
            breg[kkl][nt][0] = *(unsigned*)&h0;
            breg[kkl][nt][1] = *(unsigned*)&h1;
        }
    }

    float c_0 = 0.0f, c_1 = 0.0f;
    int sl0 = -1, sl1 = -1;
    if (sen_len) { sl0 = sen_len[b0]; sl1 = sen_len[b1]; }

    // precomputed fp16 store indices for this thread's h outputs
    const int u_cell = u0 + ug;
    const int hi0 = hidx16(b0, u_cell);
    const int hi1 = hidx16(b1, u_cell);

    for (int t = 0; t < T_LEN; t++) {
        // ---- stage this warp's k-slice of h (16 KB) via cp.async ----
        // warp slice: uint4s [warp*1024, warp*1024+1024); 32 per lane,
        // per iter 32 lanes x 16B = 512B smem stride.
        {
            const uint4* hs = (const uint4*)(g_hbuf16[t & 1]) + warp * 1024 + lane;
            unsigned sd = sh_base + (unsigned)(warp * 16384 + lane * 16);
#pragma unroll 8
            for (int i = 0; i < 32; i++)
                cp16(sd + i * 512, hs + i * 32);
            asm volatile("cp.async.commit_group;");
        }

        // ---- prefetch cell inputs (independent of h; overlaps cp.async) ----
        float p0[4], p1[4];
        if (src) {
            int r0 = src[t * NBATCH + b0];
            int r1 = src[t * NBATCH + b1];
            const float* e0 = g_E0 + (size_t)r0 * G4 + u0 + ug;
            const float* e1 = g_E0 + (size_t)r1 * G4 + u0 + ug;
#pragma unroll
            for (int gt = 0; gt < 4; gt++) { p0[gt] = e0[gt * 512]; p1[gt] = e1[gt * 512]; }
        } else {
            const float* xb = g_xW1 + (size_t)t * (G4 * 64) + (size_t)(u0 + ug) * 64;
#pragma unroll
            for (int gt = 0; gt < 4; gt++) {
                p0[gt] = xb[gt * 32768 + b0];
                p1[gt] = xb[gt * 32768 + b1];
            }
        }

        asm volatile("cp.async.wait_group 0;" ::: "memory");
        __syncwarp();

        // ---- mma: m64 x n16 x k128 partial (f16, fp32 acc) ----
        float acc[4][2][4];
#pragma unroll
        for (int mt = 0; mt < 4; mt++)
#pragma unroll
            for (int nt = 0; nt < 2; nt++)
#pragma unroll
                for (int e = 0; e < 4; e++) acc[mt][nt][e] = 0.0f;

#pragma unroll
        for (int kkl = 0; kkl < 8; kkl++) {
            int kkg = warp * 8 + kkl;
#pragma unroll
            for (int mt = 0; mt < 4; mt++) {
                uint4 a = *(const uint4*)(sh_h + ((kkg * 4 + mt) * 32 + lane) * 4);
                mma_f16(acc[mt][0], (const unsigned*)&a, breg[kkl][0]);
                mma_f16(acc[mt][1], (const unsigned*)&a, breg[kkl][1]);
            }
        }

        // ---- store partials: red[w][b][n] ----
#pragma unroll
        for (int mt = 0; mt < 4; mt++)
#pragma unroll
            for (int nt = 0; nt < 2; nt++) {
                int bb = mt * 16 + g;
                float* rp = &red[(warp * 64 + bb) * RPAD + nt * 8 + 2 * tig];
                *(float2*)rp = make_float2(acc[mt][nt][0], acc[mt][nt][1]);
                *(float2*)(rp + 8 * RPAD) = make_float2(acc[mt][nt][2], acc[mt][nt][3]);
            }
        __syncthreads();

        // ---- cell phase ----
        float z0[4], z1[4];
#pragma unroll
        for (int gt = 0; gt < 4; gt++) { z0[gt] = p0[gt]; z1[gt] = p1[gt]; }
#pragma unroll
        for (int w = 0; w < 4; w++) {
            float4 v0 = *(const float4*)&red[(w * 64 + b0) * RPAD + ug * 4];
            float4 v1 = *(const float4*)&red[(w * 64 + b1) * RPAD + ug * 4];
            z0[0] += v0.x; z0[1] += v0.y; z0[2] += v0.z; z0[3] += v0.w;
            z1[0] += v1.x; z1[1] += v1.y; z1[2] += v1.z; z1[3] += v1.w;
        }

        float i0 = sig_(z0[0]), f0 = sig_(z0[1]), gg0 = tanh_ap(z0[2]), o0 = sig_(z0[3]);
        c_0 = f0 * c_0 + i0 * gg0;
        float h0n = o0 * tanh_ap(c_0);

        float i1 = sig_(z1[0]), f1 = sig_(z1[1]), gg1 = tanh_ap(z1[2]), o1 = sig_(z1[3]);
        c_1 = f1 * c_1 + i1 * gg1;
        float h1n = o1 * tanh_ap(c_1);

        __half* hd = g_hbuf16[(t + 1) & 1];
        hd[hi0] = __float2half_rn(h0n);
        hd[hi1] = __float2half_rn(h1n);

        if (src) {
            hex[ug * 64 + b0] = h0n;
            hex[ug * 64 + b1] = h1n;
        } else {
            if (t == sl0 - 1) final_out[b0 * HID + u_cell] = h0n;
            if (t == sl1 - 1) final_out[b1 * HID + u_cell] = h1n;
        }

        // ---- grid barrier (single counter, release/acquire) ----
        __syncthreads();   // orders all hbuf/hex writes before release
        if (src && tid < 64) {
            // coalesced g_h1 write (only needed by phase-2 GEMM, after kernel)
            float4 v = make_float4(hex[tid], hex[64 + tid], hex[128 + tid], hex[192 + tid]);
            *(float4*)(g_h1 + (size_t)(t * NBATCH + tid) * HID + u0) = v;
        }
        if (tid == 0) {
            asm volatile("red.release.gpu.global.add.u32 [%0], 1;"
                         :: "l"(&g_ctr) : "memory");
            unsigned tgt = nblk * (unsigned)(t + 1);
            while (ld_acq(&g_ctr) < tgt) { }
        }
        __syncthreads();
    }
}

// ---------------------------------------------------------------------------
extern "C" void kernel_launch(void* const* d_in, const int* in_sizes, int n_in,
                              void* d_out, int out_size)
{
    const int*   src       = (const int*)  d_in[0];
    const int*   sen_len   = (const int*)  d_in[1];
    const float* emb_table = (const float*)d_in[2];
    const float* Wih0      = (const float*)d_in[3];
    const float* Whh0      = (const float*)d_in[4];
    const float* bih0      = (const float*)d_in[5];
    const float* bhh0      = (const float*)d_in[6];
    const float* Wih1      = (const float*)d_in[7];
    const float* Whh1      = (const float*)d_in[8];
    const float* bih1      = (const float*)d_in[9];
    const float* bhh1      = (const float*)d_in[10];
    float* out = (float*)d_out;

    const size_t gemm_smem = (size_t)4 * GBUF * sizeof(unsigned);     // 73728 B
    const size_t scan_smem =
        (size_t)(16384 + 4 * 64 * RPAD + 256) * sizeof(unsigned);     // 87040 B
    cudaFuncSetAttribute(gemm_tf32_kernel,
                         cudaFuncAttributeMaxDynamicSharedMemorySize, (int)gemm_smem);
    cudaFuncSetAttribute(lstm_scan_kernel,
                         cudaFuncAttributeMaxDynamicSharedMemorySize, (int)scan_smem);

    // Phase 0: E0 = emb_table @ Wih0^T + b0   (10000 x 2048)
    {
        dim3 grid(G4 / 128, (NVOCAB + 127) / 128);
        gemm_tf32_kernel<<<grid, 256, gemm_smem>>>(emb_table, Wih0, bih0, bhh0, 0, NVOCAB);
    }

    // Phase 1: layer-0 scan
    zero_init_kernel<<<64, 512>>>();
    lstm_scan_kernel<<<SCAN_BLOCKS, SCAN_THREADS, scan_smem>>>(
        src, Whh0, nullptr, nullptr);

    // Phase 2: xW1 = h1 @ Wih1^T + b1  -> transposed [t][r][b]
    {
        dim3 grid(G4 / 128, (T_LEN * NBATCH) / 128);
        gemm_tf32_kernel<<<grid, 256, gemm_smem>>>(nullptr, Wih1, bih1, bhh1, 1,
                                                   T_LEN * NBATCH);
    }

    // Phase 3: layer-1 scan (+ final gather at sen_len-1)
    zero_init_kernel<<<64, 512>>>();
    lstm_scan_kernel<<<SCAN_BLOCKS, SCAN_THREADS, scan_smem>>>(
        nullptr, Whh1, sen_len, out);
}